// round 14
// baseline (speedup 1.0000x reference)
#include <cuda_runtime.h>
#include <math.h>

#define NN 100000
#define EE 3200000
#define HID 16
#define NCLS 10
#define KK 50000
#define SSIZE 131072
#define TILE 4096
#define SBLK 1024
#define NBLK 98   // ceil(100000/1024)

typedef unsigned long long ull;

__device__ float  d_h0[NN * HID];
__device__ float  d_h[NN * HID];
__device__ int    d_cnt[NN];          // zero at load; scanACS re-zeroes each exec
__device__ int    d_rowptr[NN + 1];
__device__ float  d_dinv[NN];
__device__ int    d_csr[EE];
__device__ int    d_rank[EE];
__device__ float  d_spart[NN];
__device__ float  d_t2[NN];
__device__ float  d_s[NN];
__device__ ull    d_keys[SSIZE];      // zero at load; sort permutes zero tail in place
__device__ int    d_nidx[NN];
__device__ int    d_perm[KK];
__device__ float4 d_h2v[NN * 3];
__device__ float  d_dinv2[KK];
__device__ int    d_bsum[NBLK];
__device__ int    d_gbar_cnt;
__device__ int    d_gbar_gen;

__device__ __forceinline__ void kadd(float& s, float& c, float v) {
    float y = v - c;
    float t = s + y;
    c = (t - s) - y;
    s = t;
}

__device__ __forceinline__ float rsqrt_acc(float x) {
    float r = rsqrtf(x);
    return r * (1.5f - 0.5f * x * r * r);
}

// software grid barrier (N co-resident blocks; generation-based, reusable)
template <int N>
__device__ __forceinline__ void gridbar() {
    __syncthreads();
    if (threadIdx.x == 0) {
        __threadfence();
        int gen = atomicAdd(&d_gbar_gen, 0);
        if (atomicAdd(&d_gbar_cnt, 1) == N - 1) {
            d_gbar_cnt = 0;
            __threadfence();
            atomicExch(&d_gbar_gen, gen + 1);
        } else {
            while (atomicAdd(&d_gbar_gen, 0) == gen) { __nanosleep(64); }
        }
    }
    __syncthreads();
}

// h0 = x @ w1 : f32x2 packed FMA, 2 nodes x 16ch per thread, split-k over
// lane pairs (h = t&1 owns k-half h).
__global__ void __launch_bounds__(256) kgemm1(const float* __restrict__ x,
                                              const float* __restrict__ w1) {
    __shared__ __align__(16) float xsbuf[2 * (256 * 17) + 1];
    __shared__ __align__(16) float ws[2050];
    int t = threadIdx.x;
    for (int f = t; f < 2048; f += 256) {
        int kk = f >> 4;
        ws[f + ((kk >= 64) ? 2 : 0)] = w1[f];
    }
    const ull* wsu = (const ull*)ws;
    int base = blockIdx.x * 256;
    int p = t >> 1, h = t & 1;
    float* xs0 = xsbuf;
    float* xs1 = xsbuf + 256 * 17 + 1;
    ull a0[8], a1[8];
#pragma unroll
    for (int q8 = 0; q8 < 8; q8++) { a0[q8] = 0ull; a1[q8] = 0ull; }

    for (int it = 0; it < 4; it++) {
        __syncthreads();
#pragma unroll
        for (int half = 0; half < 2; half++) {
            int kq0 = (half * 4 + it) * 4;
            float* dst = half ? xs1 : xs0;
#pragma unroll
            for (int j = 0; j < 4; j++) {
                int idx = j * 256 + t;
                int row = idx >> 2, q = idx & 3;
                int rg = base + row; if (rg >= NN) rg = NN - 1;
                float4 v = ((const float4*)x)[rg * 32 + kq0 + q];
                float* xr = dst + row * 17 + q * 4;
                xr[0] = v.x; xr[1] = v.y; xr[2] = v.z; xr[3] = v.w;
            }
        }
        __syncthreads();
        const float* myxs = h ? xs1 : xs0;
        int prow = (p * 2) * 17;
#pragma unroll
        for (int k = 0; k < 16; k++) {
            float xv0 = myxs[prow + k];
            float xv1 = myxs[prow + 17 + k];
            ull xx0, xx1;
            asm("mov.b64 %0, {%1, %1};" : "=l"(xx0) : "r"(__float_as_uint(xv0)));
            asm("mov.b64 %0, {%1, %1};" : "=l"(xx1) : "r"(__float_as_uint(xv1)));
            int kk = (h * 4 + it) * 16 + k;
            int wb = kk * 8 + h;
#pragma unroll
            for (int q8 = 0; q8 < 8; q8++) {
                ull wv = wsu[wb + q8];
                asm("fma.rn.f32x2 %0, %1, %2, %0;" : "+l"(a0[q8]) : "l"(xx0), "l"(wv));
                asm("fma.rn.f32x2 %0, %1, %2, %0;" : "+l"(a1[q8]) : "l"(xx1), "l"(wv));
            }
        }
    }
#pragma unroll
    for (int q8 = 0; q8 < 8; q8++) {
        ull o0 = __shfl_xor_sync(0xFFFFFFFFu, a0[q8], 1);
        ull o1 = __shfl_xor_sync(0xFFFFFFFFu, a1[q8], 1);
        asm("add.rn.f32x2 %0, %0, %1;" : "+l"(a0[q8]) : "l"(o0));
        asm("add.rn.f32x2 %0, %0, %1;" : "+l"(a1[q8]) : "l"(o1));
    }
    if (h == 0) {
        int n0 = base + p * 2;
        if (n0 < NN) {
            ull* o = (ull*)(d_h0 + (size_t)n0 * HID);
#pragma unroll
            for (int q8 = 0; q8 < 8; q8++) o[q8] = a0[q8];
        }
        if (n0 + 1 < NN) {
            ull* o = (ull*)(d_h0 + (size_t)(n0 + 1) * HID);
#pragma unroll
            for (int q8 = 0; q8 < 8; q8++) o[q8] = a1[q8];
        }
    }
}

// count in-degrees; record each edge's rank within its dst bucket
__global__ void kcount(const int* __restrict__ ei) {
    int e4 = blockIdx.x * blockDim.x + threadIdx.x;
    int4 d = ((const int4*)(ei + EE))[e4];
    int4 r;
    r.x = atomicAdd(&d_cnt[d.x], 1);
    r.y = atomicAdd(&d_cnt[d.y], 1);
    r.z = atomicAdd(&d_cnt[d.z], 1);
    r.w = atomicAdd(&d_cnt[d.w], 1);
    ((int4*)d_rank)[e4] = r;
}

// fused persistent: block sums -> gridbar -> prefix/derived -> gridbar -> scatter
__global__ void __launch_bounds__(SBLK) kscanACS(const int* __restrict__ ei) {
    __shared__ int ws[32];
    __shared__ int off_s;
    int bid = blockIdx.x;
    int t = threadIdx.x, lane = t & 31, wd = t >> 5;
    int i = bid * SBLK + t;
    int v = (i < NN) ? d_cnt[i] : 0;

    // phase A: block sum
    {
        int s = v;
#pragma unroll
        for (int o = 16; o; o >>= 1) s += __shfl_xor_sync(0xFFFFFFFFu, s, o);
        if (lane == 0) ws[wd] = s;
        __syncthreads();
        if (wd == 0) {
            int s2 = ws[lane];
#pragma unroll
            for (int o = 16; o; o >>= 1) s2 += __shfl_xor_sync(0xFFFFFFFFu, s2, o);
            if (lane == 0) d_bsum[bid] = s2;
        }
    }
    gridbar<NBLK>();

    // phase C: offset + local exclusive scan + derived arrays
    if (wd == 0) {
        int acc = 0;
        for (int b = lane; b < bid; b += 32) acc += __ldcg(&d_bsum[b]);
#pragma unroll
        for (int o = 16; o; o >>= 1) acc += __shfl_xor_sync(0xFFFFFFFFu, acc, o);
        if (lane == 0) {
            off_s = acc;
            if (bid == NBLK - 1) d_rowptr[NN] = acc + __ldcg(&d_bsum[NBLK - 1]);
        }
    }
    __syncthreads();
    {
        int xv = v;
#pragma unroll
        for (int o = 1; o < 32; o <<= 1) {
            int y = __shfl_up_sync(0xFFFFFFFFu, xv, o);
            if (lane >= o) xv += y;
        }
        if (lane == 31) ws[wd] = xv;
        __syncthreads();
        if (wd == 0) {
            int s2 = ws[lane];
#pragma unroll
            for (int o = 1; o < 32; o <<= 1) {
                int y = __shfl_up_sync(0xFFFFFFFFu, s2, o);
                if (lane >= o) s2 += y;
            }
            ws[lane] = s2;
        }
        __syncthreads();
        int excl = xv - v + (wd > 0 ? ws[wd - 1] : 0) + off_s;
        if (i < NN) {
            d_rowptr[i] = excl;
            d_dinv[i] = rsqrt_acc((float)(v + 1));
            d_nidx[i] = -1;
            d_cnt[i] = 0;
        }
    }
    gridbar<NBLK>();

    // phase S: atomic-free scatter (all rowptr entries now valid)
    int nthreads = NBLK * SBLK;
    for (int e4 = bid * SBLK + t; e4 < EE / 4; e4 += nthreads) {
        int4 s = ((const int4*)ei)[e4];
        int4 d = ((const int4*)(ei + EE))[e4];
        int4 r = ((const int4*)d_rank)[e4];
        d_csr[__ldcg(&d_rowptr[d.x]) + r.x] = s.x;
        d_csr[__ldcg(&d_rowptr[d.y]) + r.y] = s.y;
        d_csr[__ldcg(&d_rowptr[d.z]) + r.z] = s.z;
        d_csr[__ldcg(&d_rowptr[d.w]) + r.w] = s.w;
    }
}

// conv1 (+relu) fp32 Kahan accumulation, 4-way unrolled; score linear terms
__global__ void kconv1(const float* __restrict__ b1, const float* __restrict__ pw1,
                       const float* __restrict__ pw2, const float* __restrict__ pb) {
    int gw = (blockIdx.x * blockDim.x + threadIdx.x) >> 5;
    if (gw >= NN) return;
    int lane = threadIdx.x & 31, half = lane >> 4, ch = lane & 15;
    int st = d_rowptr[gw], en = d_rowptr[gw + 1];
    float s0a = 0.f, c0a = 0.f, s1a = 0.f, c1a = 0.f;
    float s2a = 0.f, c2a = 0.f, s3a = 0.f, c3a = 0.f;
    int e = st + half;
    for (; e + 6 < en; e += 8) {
        int n0 = d_csr[e], n1 = d_csr[e + 2], n2 = d_csr[e + 4], n3 = d_csr[e + 6];
        kadd(s0a, c0a, d_dinv[n0] * d_h0[n0 * HID + ch]);
        kadd(s1a, c1a, d_dinv[n1] * d_h0[n1 * HID + ch]);
        kadd(s2a, c2a, d_dinv[n2] * d_h0[n2 * HID + ch]);
        kadd(s3a, c3a, d_dinv[n3] * d_h0[n3 * HID + ch]);
    }
    for (; e < en; e += 2) {
        int n0 = d_csr[e];
        kadd(s0a, c0a, d_dinv[n0] * d_h0[n0 * HID + ch]);
    }
    kadd(s0a, c0a, s1a); kadd(s0a, c0a, -c1a);
    kadd(s0a, c0a, s2a); kadd(s0a, c0a, -c2a);
    kadd(s0a, c0a, s3a); kadd(s0a, c0a, -c3a);
    float os = __shfl_xor_sync(0xFFFFFFFFu, s0a, 16);
    float oc = __shfl_xor_sync(0xFFFFFFFFu, c0a, 16);
    kadd(s0a, c0a, os); kadd(s0a, c0a, -oc);
    float a = s0a - c0a;
    float degf = (float)(en - st + 1);
    float hv = d_dinv[gw] * a + d_h0[gw * HID + ch] / degf + b1[ch];
    hv = fmaxf(hv, 0.f);
    if (half == 0) d_h[gw * HID + ch] = hv;
    float u1 = hv * pw1[ch];
    float u2 = hv * pw2[ch];
#pragma unroll
    for (int o = 8; o; o >>= 1) {
        u1 += __shfl_xor_sync(0xFFFFFFFFu, u1, o);
        u2 += __shfl_xor_sync(0xFFFFFFFFu, u2, o);
    }
    if (lane == 0) { d_spart[gw] = u1 + pb[0]; d_t2[gw] = u2; }
}

// score = spart + sum_{in-neighbors} t2 (Kahan); build sort key
__global__ void kpool() {
    int gw = (blockIdx.x * blockDim.x + threadIdx.x) >> 5;
    if (gw >= NN) return;
    int lane = threadIdx.x & 31;
    int st = d_rowptr[gw], en = d_rowptr[gw + 1];
    float sum = 0.f, comp = 0.f;
    for (int e = st + lane; e < en; e += 32) kadd(sum, comp, d_t2[d_csr[e]]);
#pragma unroll
    for (int o = 16; o; o >>= 1) {
        float os = __shfl_xor_sync(0xFFFFFFFFu, sum, o);
        float oc = __shfl_xor_sync(0xFFFFFFFFu, comp, o);
        kadd(sum, comp, os); kadd(sum, comp, -oc);
    }
    if (lane == 0) {
        float sv = d_spart[gw] + (sum - comp);
        d_s[gw] = sv;
        unsigned u = __float_as_uint(sv);
        u = (u & 0x80000000u) ? ~u : (u | 0x80000000u);
        d_keys[gw] = ((ull)u << 32) | (ull)(~(unsigned)gw);
    }
}

// bitonic sort, descending, SSIZE keys (tail = all-zero padding keys)
__global__ void __launch_bounds__(1024) ksort_init() {
    __shared__ ull sk[TILE];
    int base = blockIdx.x * TILE;
    for (int i = threadIdx.x; i < TILE; i += 1024) sk[i] = d_keys[base + i];
    __syncthreads();
    for (int k = 2; k <= TILE; k <<= 1)
        for (int j = k >> 1; j > 0; j >>= 1) {
            for (int i = threadIdx.x; i < TILE; i += 1024) {
                int p = i ^ j;
                if (p > i) {
                    bool desc = (((base + i) & k) == 0);
                    ull A = sk[i], B = sk[p];
                    if ((A < B) == desc) { sk[i] = B; sk[p] = A; }
                }
            }
            __syncthreads();
        }
    for (int i = threadIdx.x; i < TILE; i += 1024) d_keys[base + i] = sk[i];
}

// all global steps (j >= 4096) of phase k, fused.
__global__ void __launch_bounds__(1024) kcol(int k) {
    __shared__ ull sk[4096];
    int lowbase = blockIdx.x * 128;
    for (int idx = threadIdx.x; idx < 4096; idx += 1024) {
        int m = idx >> 7, low = idx & 127;
        sk[idx] = d_keys[m * 4096 + lowbase + low];
    }
    __syncthreads();
    int kp = k >> 12;
    for (int jp = kp >> 1; jp >= 1; jp >>= 1) {
        for (int q = threadIdx.x; q < 2048; q += 1024) {
            int low = q & 127;
            int mg = q >> 7;
            int m = ((mg & ~(jp - 1)) << 1) | (mg & (jp - 1));
            int p = m | jp;
            bool desc = ((m & kp) == 0);
            ull A = sk[m * 128 + low], B = sk[p * 128 + low];
            if ((A < B) == desc) { sk[m * 128 + low] = B; sk[p * 128 + low] = A; }
        }
        __syncthreads();
    }
    for (int idx = threadIdx.x; idx < 4096; idx += 1024) {
        int m = idx >> 7, low = idx & 127;
        d_keys[m * 4096 + lowbase + low] = sk[idx];
    }
}

__global__ void __launch_bounds__(1024) ksort_merge(int k) {
    __shared__ ull sk[TILE];
    int base = blockIdx.x * TILE;
    for (int i = threadIdx.x; i < TILE; i += 1024) sk[i] = d_keys[base + i];
    __syncthreads();
    for (int j = TILE >> 1; j > 0; j >>= 1) {
        for (int i = threadIdx.x; i < TILE; i += 1024) {
            int p = i ^ j;
            if (p > i) {
                bool desc = (((base + i) & k) == 0);
                ull A = sk[i], B = sk[p];
                if ((A < B) == desc) { sk[i] = B; sk[p] = A; }
            }
        }
        __syncthreads();
    }
    for (int i = threadIdx.x; i < TILE; i += 1024) d_keys[base + i] = sk[i];
}

// top-K select: perm, inverse map, h2v[orig id] = tanh(s) * (h @ w2)
__global__ void kselect(const float* __restrict__ w2) {
    int r = (blockIdx.x * blockDim.x + threadIdx.x) >> 5;
    if (r >= KK) return;
    int lane = threadIdx.x & 31;
    ull key = d_keys[r];
    int idx = (int)(~(unsigned)(key & 0xFFFFFFFFull));
    if (lane == 0) { d_nidx[idx] = r; d_perm[r] = idx; }
    if (lane < NCLS) {
        float th = tanhf(d_s[idx]);
        float acc = 0.f;
#pragma unroll
        for (int j = 0; j < HID; j++)
            acc += d_h[idx * HID + j] * w2[j * NCLS + lane];
        ((float*)d_h2v)[idx * 12 + lane] = th * acc;
    }
}

// surviving-degree of kept nodes; pre-scale h2v rows by dinv2
__global__ void kdeg2() {
    int r = (blockIdx.x * blockDim.x + threadIdx.x) >> 5;
    if (r >= KK) return;
    int lane = threadIdx.x & 31;
    int i = d_perm[r];
    int st = d_rowptr[i], en = d_rowptr[i + 1];
    int cnt = 0;
    for (int e = st + lane; e < en; e += 32) cnt += (d_nidx[d_csr[e]] >= 0);
#pragma unroll
    for (int o = 16; o; o >>= 1) cnt += __shfl_xor_sync(0xFFFFFFFFu, cnt, o);
    float d2 = rsqrt_acc((float)(cnt + 1));
    if (lane == 0) d_dinv2[r] = d2;
    if (lane < 12) ((float*)d_h2v)[i * 12 + lane] *= d2;
}

// conv2: branch-free float4 gathers from dense h2v + relu + log_softmax
__global__ void kconv2(const float* __restrict__ b2, float* __restrict__ out) {
    __shared__ __align__(16) float red[8][12];
    int r = (blockIdx.x * blockDim.x + threadIdx.x) >> 5;
    if (r >= KK) return;
    int lane = threadIdx.x & 31, wip = (threadIdx.x >> 5) & 7;
    int i = d_perm[r];
    int st = d_rowptr[i], en = d_rowptr[i + 1];
    const float* h2vf = (const float*)d_h2v;
    float4 a0 = {0,0,0,0}, a1 = {0,0,0,0}, a2 = {0,0,0,0};
    for (int e = st + lane; e < en; e += 32) {
        int n = d_csr[e];
        const float4* row = (const float4*)(h2vf + n * 12);
        float4 v0 = row[0], v1 = row[1], v2 = row[2];
        a0.x += v0.x; a0.y += v0.y; a0.z += v0.z; a0.w += v0.w;
        a1.x += v1.x; a1.y += v1.y; a1.z += v1.z; a1.w += v1.w;
        a2.x += v2.x; a2.y += v2.y; a2.z += v2.z; a2.w += v2.w;
    }
#pragma unroll
    for (int o = 16; o; o >>= 1) {
        a0.x += __shfl_xor_sync(0xFFFFFFFFu, a0.x, o);
        a0.y += __shfl_xor_sync(0xFFFFFFFFu, a0.y, o);
        a0.z += __shfl_xor_sync(0xFFFFFFFFu, a0.z, o);
        a0.w += __shfl_xor_sync(0xFFFFFFFFu, a0.w, o);
        a1.x += __shfl_xor_sync(0xFFFFFFFFu, a1.x, o);
        a1.y += __shfl_xor_sync(0xFFFFFFFFu, a1.y, o);
        a1.z += __shfl_xor_sync(0xFFFFFFFFu, a1.z, o);
        a1.w += __shfl_xor_sync(0xFFFFFFFFu, a1.w, o);
        a2.x += __shfl_xor_sync(0xFFFFFFFFu, a2.x, o);
        a2.y += __shfl_xor_sync(0xFFFFFFFFu, a2.y, o);
    }
    if (lane == 0) {
        ((float4*)red[wip])[0] = a0;
        ((float4*)red[wip])[1] = a1;
        ((float4*)red[wip])[2] = a2;
    }
    __syncwarp();
    bool act = lane < NCLS;
    float own = act ? h2vf[i * 12 + lane] : 0.f;
    float v = act
        ? fmaxf(d_dinv2[r] * (red[wip][lane] + own) + b2[lane], 0.f)
        : -1e30f;
    float m = v;
#pragma unroll
    for (int o = 8; o; o >>= 1)
        m = fmaxf(m, __shfl_xor_sync(0xFFFFFFFFu, m, o, 16));
    float ex = act ? expf(v - m) : 0.f;
#pragma unroll
    for (int o = 8; o; o >>= 1)
        ex += __shfl_xor_sync(0xFFFFFFFFu, ex, o, 16);
    if (act) out[r * NCLS + lane] = v - m - logf(ex);
}

extern "C" void kernel_launch(void* const* d_in, const int* in_sizes, int n_in,
                              void* d_out, int out_size) {
    const float* x  = (const float*)d_in[0];
    const int*   ei = (const int*)d_in[1];
    const float* w1 = (const float*)d_in[2];
    const float* b1 = (const float*)d_in[3];
    const float* pw1 = (const float*)d_in[4];
    const float* pw2 = (const float*)d_in[5];
    const float* pb = (const float*)d_in[6];
    const float* w2 = (const float*)d_in[7];
    const float* b2 = (const float*)d_in[8];
    float* out = (float*)d_out;

    kcount<<<EE / 1024, 256>>>(ei);
    kgemm1<<<(NN + 255) / 256, 256>>>(x, w1);
    kscanACS<<<NBLK, SBLK>>>(ei);
    kconv1<<<NN * 32 / 256, 256>>>(b1, pw1, pw2, pb);   // slot 4: gets profiled
    kpool<<<NN * 32 / 256, 256>>>();

    ksort_init<<<SSIZE / TILE, 1024>>>();
    for (int k = TILE * 2; k <= SSIZE; k <<= 1) {
        kcol<<<SSIZE / 4096, 1024>>>(k);
        ksort_merge<<<SSIZE / TILE, 1024>>>(k);
    }

    kselect<<<KK * 32 / 256, 256>>>(w2);
    kdeg2<<<KK * 32 / 256, 256>>>();
    kconv2<<<KK * 32 / 256, 256>>>(b2, out);
}

// round 15
// speedup vs baseline: 1.0458x; 1.0458x over previous
#include <cuda_runtime.h>
#include <math.h>

#define NN 100000
#define EE 3200000
#define HID 16
#define NCLS 10
#define KK 50000
#define SSIZE 131072
#define TILE 4096
#define SBLK 1024
#define NBLK 98   // ceil(100000/1024)

typedef unsigned long long ull;

__device__ float  d_h0[NN * HID];
__device__ float  d_g0[NN * HID];     // dinv[n] * h0[n][ch] (same products as inline)
__device__ float  d_h[NN * HID];
__device__ int    d_cnt[NN];          // zero at load; scanC re-zeroes each exec
__device__ int    d_rowptr[NN + 1];
__device__ float  d_dinv[NN];
__device__ int    d_csr[EE];
__device__ int    d_rank[EE];
__device__ float  d_spart[NN];
__device__ float  d_t2[NN];
__device__ float  d_s[NN];
__device__ ull    d_keys[SSIZE];      // zero at load; sort permutes zero tail in place
__device__ int    d_nidx[NN];
__device__ int    d_perm[KK];
__device__ float4 d_h2v[NN * 3];
__device__ float  d_dinv2[KK];
__device__ int    d_bsum[NBLK];

__device__ __forceinline__ void kadd(float& s, float& c, float v) {
    float y = v - c;
    float t = s + y;
    c = (t - s) - y;
    s = t;
}

__device__ __forceinline__ float rsqrt_acc(float x) {
    float r = rsqrtf(x);
    return r * (1.5f - 0.5f * x * r * r);
}

// h0 = x @ w1 (f32x2 packed FMA, 2 nodes x 16ch/thread, split-k over lane
// pairs). Epilogue also writes g0 = dinv * h0 (packed muls).
__global__ void __launch_bounds__(256) kgemm1(const float* __restrict__ x,
                                              const float* __restrict__ w1) {
    __shared__ __align__(16) float xsbuf[2 * (256 * 17) + 1];
    __shared__ __align__(16) float ws[2050];
    int t = threadIdx.x;
    for (int f = t; f < 2048; f += 256) {
        int kk = f >> 4;
        ws[f + ((kk >= 64) ? 2 : 0)] = w1[f];
    }
    const ull* wsu = (const ull*)ws;
    int base = blockIdx.x * 256;
    int p = t >> 1, h = t & 1;
    float* xs0 = xsbuf;
    float* xs1 = xsbuf + 256 * 17 + 1;
    ull a0[8], a1[8];
#pragma unroll
    for (int q8 = 0; q8 < 8; q8++) { a0[q8] = 0ull; a1[q8] = 0ull; }

    for (int it = 0; it < 4; it++) {
        __syncthreads();
#pragma unroll
        for (int half = 0; half < 2; half++) {
            int kq0 = (half * 4 + it) * 4;
            float* dst = half ? xs1 : xs0;
#pragma unroll
            for (int j = 0; j < 4; j++) {
                int idx = j * 256 + t;
                int row = idx >> 2, q = idx & 3;
                int rg = base + row; if (rg >= NN) rg = NN - 1;
                float4 v = ((const float4*)x)[rg * 32 + kq0 + q];
                float* xr = dst + row * 17 + q * 4;
                xr[0] = v.x; xr[1] = v.y; xr[2] = v.z; xr[3] = v.w;
            }
        }
        __syncthreads();
        const float* myxs = h ? xs1 : xs0;
        int prow = (p * 2) * 17;
#pragma unroll
        for (int k = 0; k < 16; k++) {
            float xv0 = myxs[prow + k];
            float xv1 = myxs[prow + 17 + k];
            ull xx0, xx1;
            asm("mov.b64 %0, {%1, %1};" : "=l"(xx0) : "r"(__float_as_uint(xv0)));
            asm("mov.b64 %0, {%1, %1};" : "=l"(xx1) : "r"(__float_as_uint(xv1)));
            int kk = (h * 4 + it) * 16 + k;
            int wb = kk * 8 + h;
#pragma unroll
            for (int q8 = 0; q8 < 8; q8++) {
                ull wv = wsu[wb + q8];
                asm("fma.rn.f32x2 %0, %1, %2, %0;" : "+l"(a0[q8]) : "l"(xx0), "l"(wv));
                asm("fma.rn.f32x2 %0, %1, %2, %0;" : "+l"(a1[q8]) : "l"(xx1), "l"(wv));
            }
        }
    }
#pragma unroll
    for (int q8 = 0; q8 < 8; q8++) {
        ull o0 = __shfl_xor_sync(0xFFFFFFFFu, a0[q8], 1);
        ull o1 = __shfl_xor_sync(0xFFFFFFFFu, a1[q8], 1);
        asm("add.rn.f32x2 %0, %0, %1;" : "+l"(a0[q8]) : "l"(o0));
        asm("add.rn.f32x2 %0, %0, %1;" : "+l"(a1[q8]) : "l"(o1));
    }
    if (h == 0) {
        int n0 = base + p * 2;
        if (n0 < NN) {
            ull dvp; unsigned dv = __float_as_uint(d_dinv[n0]);
            asm("mov.b64 %0, {%1, %1};" : "=l"(dvp) : "r"(dv));
            ull* o = (ull*)(d_h0 + (size_t)n0 * HID);
            ull* g = (ull*)(d_g0 + (size_t)n0 * HID);
#pragma unroll
            for (int q8 = 0; q8 < 8; q8++) {
                o[q8] = a0[q8];
                ull gv;
                asm("mul.rn.f32x2 %0, %1, %2;" : "=l"(gv) : "l"(a0[q8]), "l"(dvp));
                g[q8] = gv;
            }
        }
        if (n0 + 1 < NN) {
            ull dvp; unsigned dv = __float_as_uint(d_dinv[n0 + 1]);
            asm("mov.b64 %0, {%1, %1};" : "=l"(dvp) : "r"(dv));
            ull* o = (ull*)(d_h0 + (size_t)(n0 + 1) * HID);
            ull* g = (ull*)(d_g0 + (size_t)(n0 + 1) * HID);
#pragma unroll
            for (int q8 = 0; q8 < 8; q8++) {
                o[q8] = a1[q8];
                ull gv;
                asm("mul.rn.f32x2 %0, %1, %2;" : "=l"(gv) : "l"(a1[q8]), "l"(dvp));
                g[q8] = gv;
            }
        }
    }
}

// count in-degrees; record each edge's rank within its dst bucket
__global__ void kcount(const int* __restrict__ ei) {
    int e4 = blockIdx.x * blockDim.x + threadIdx.x;
    int4 d = ((const int4*)(ei + EE))[e4];
    int4 r;
    r.x = atomicAdd(&d_cnt[d.x], 1);
    r.y = atomicAdd(&d_cnt[d.y], 1);
    r.z = atomicAdd(&d_cnt[d.z], 1);
    r.w = atomicAdd(&d_cnt[d.w], 1);
    ((int4*)d_rank)[e4] = r;
}

__global__ void __launch_bounds__(SBLK) kscanA() {
    __shared__ int ws[32];
    int i = blockIdx.x * SBLK + threadIdx.x;
    int lane = threadIdx.x & 31, wd = threadIdx.x >> 5;
    int v = (i < NN) ? d_cnt[i] : 0;
    int s = v;
#pragma unroll
    for (int o = 16; o; o >>= 1) s += __shfl_xor_sync(0xFFFFFFFFu, s, o);
    if (lane == 0) ws[wd] = s;
    __syncthreads();
    if (wd == 0) {
        int s2 = ws[lane];
#pragma unroll
        for (int o = 16; o; o >>= 1) s2 += __shfl_xor_sync(0xFFFFFFFFu, s2, o);
        if (lane == 0) d_bsum[blockIdx.x] = s2;
    }
}

__global__ void __launch_bounds__(SBLK) kscanC() {
    __shared__ int ws[32];
    __shared__ int off_s;
    int bid = blockIdx.x;
    int t = threadIdx.x, lane = t & 31, wd = t >> 5;
    if (wd == 0) {
        int acc = 0;
        for (int b = lane; b < bid; b += 32) acc += d_bsum[b];
#pragma unroll
        for (int o = 16; o; o >>= 1) acc += __shfl_xor_sync(0xFFFFFFFFu, acc, o);
        if (lane == 0) {
            off_s = acc;
            if (bid == NBLK - 1) d_rowptr[NN] = acc + d_bsum[NBLK - 1];
        }
    }
    int i = bid * SBLK + t;
    int v = (i < NN) ? d_cnt[i] : 0;
    int xv = v;
#pragma unroll
    for (int o = 1; o < 32; o <<= 1) {
        int y = __shfl_up_sync(0xFFFFFFFFu, xv, o);
        if (lane >= o) xv += y;
    }
    if (lane == 31) ws[wd] = xv;
    __syncthreads();
    if (wd == 0) {
        int s2 = ws[lane];
#pragma unroll
        for (int o = 1; o < 32; o <<= 1) {
            int y = __shfl_up_sync(0xFFFFFFFFu, s2, o);
            if (lane >= o) s2 += y;
        }
        ws[lane] = s2;
    }
    __syncthreads();
    int excl = xv - v + (wd > 0 ? ws[wd - 1] : 0) + off_s;
    if (i < NN) {
        d_rowptr[i] = excl;
        d_dinv[i] = rsqrt_acc((float)(v + 1));
        d_nidx[i] = -1;
        d_cnt[i] = 0;
    }
}

// atomic-free scatter: position = rowptr[dst] + rank[edge]
__global__ void kscatter(const int* __restrict__ ei) {
    int e4 = blockIdx.x * blockDim.x + threadIdx.x;
    int4 s = ((const int4*)ei)[e4];
    int4 d = ((const int4*)(ei + EE))[e4];
    int4 r = ((const int4*)d_rank)[e4];
    d_csr[d_rowptr[d.x] + r.x] = s.x;
    d_csr[d_rowptr[d.y] + r.y] = s.y;
    d_csr[d_rowptr[d.z] + r.z] = s.z;
    d_csr[d_rowptr[d.w] + r.w] = s.w;
}

// conv1 (+relu): Kahan over precomputed g0 gathers; score linear terms fused
__global__ void kconv1(const float* __restrict__ b1, const float* __restrict__ pw1,
                       const float* __restrict__ pw2, const float* __restrict__ pb) {
    int gw = (blockIdx.x * blockDim.x + threadIdx.x) >> 5;
    if (gw >= NN) return;
    int lane = threadIdx.x & 31, half = lane >> 4, ch = lane & 15;
    int st = d_rowptr[gw], en = d_rowptr[gw + 1];
    float s0a = 0.f, c0a = 0.f, s1a = 0.f, c1a = 0.f;
    float s2a = 0.f, c2a = 0.f, s3a = 0.f, c3a = 0.f;
    int e = st + half;
    for (; e + 6 < en; e += 8) {
        int n0 = d_csr[e], n1 = d_csr[e + 2], n2 = d_csr[e + 4], n3 = d_csr[e + 6];
        kadd(s0a, c0a, d_g0[n0 * HID + ch]);
        kadd(s1a, c1a, d_g0[n1 * HID + ch]);
        kadd(s2a, c2a, d_g0[n2 * HID + ch]);
        kadd(s3a, c3a, d_g0[n3 * HID + ch]);
    }
    for (; e < en; e += 2) {
        int n0 = d_csr[e];
        kadd(s0a, c0a, d_g0[n0 * HID + ch]);
    }
    kadd(s0a, c0a, s1a); kadd(s0a, c0a, -c1a);
    kadd(s0a, c0a, s2a); kadd(s0a, c0a, -c2a);
    kadd(s0a, c0a, s3a); kadd(s0a, c0a, -c3a);
    float os = __shfl_xor_sync(0xFFFFFFFFu, s0a, 16);
    float oc = __shfl_xor_sync(0xFFFFFFFFu, c0a, 16);
    kadd(s0a, c0a, os); kadd(s0a, c0a, -oc);
    float a = s0a - c0a;
    float degf = (float)(en - st + 1);
    float hv = d_dinv[gw] * a + d_h0[gw * HID + ch] / degf + b1[ch];
    hv = fmaxf(hv, 0.f);
    if (half == 0) d_h[gw * HID + ch] = hv;
    float u1 = hv * pw1[ch];
    float u2 = hv * pw2[ch];
#pragma unroll
    for (int o = 8; o; o >>= 1) {
        u1 += __shfl_xor_sync(0xFFFFFFFFu, u1, o);
        u2 += __shfl_xor_sync(0xFFFFFFFFu, u2, o);
    }
    if (lane == 0) { d_spart[gw] = u1 + pb[0]; d_t2[gw] = u2; }
}

// score = spart + sum_{in-neighbors} t2 (Kahan); build sort key
__global__ void kpool() {
    int gw = (blockIdx.x * blockDim.x + threadIdx.x) >> 5;
    if (gw >= NN) return;
    int lane = threadIdx.x & 31;
    int st = d_rowptr[gw], en = d_rowptr[gw + 1];
    float sum = 0.f, comp = 0.f;
    for (int e = st + lane; e < en; e += 32) kadd(sum, comp, d_t2[d_csr[e]]);
#pragma unroll
    for (int o = 16; o; o >>= 1) {
        float os = __shfl_xor_sync(0xFFFFFFFFu, sum, o);
        float oc = __shfl_xor_sync(0xFFFFFFFFu, comp, o);
        kadd(sum, comp, os); kadd(sum, comp, -oc);
    }
    if (lane == 0) {
        float sv = d_spart[gw] + (sum - comp);
        d_s[gw] = sv;
        unsigned u = __float_as_uint(sv);
        u = (u & 0x80000000u) ? ~u : (u | 0x80000000u);
        d_keys[gw] = ((ull)u << 32) | (ull)(~(unsigned)gw);
    }
}

// bitonic sort, descending, SSIZE keys (tail = all-zero padding keys)
__global__ void __launch_bounds__(1024) ksort_init() {
    __shared__ ull sk[TILE];
    int base = blockIdx.x * TILE;
    for (int i = threadIdx.x; i < TILE; i += 1024) sk[i] = d_keys[base + i];
    __syncthreads();
    for (int k = 2; k <= TILE; k <<= 1)
        for (int j = k >> 1; j > 0; j >>= 1) {
            for (int i = threadIdx.x; i < TILE; i += 1024) {
                int p = i ^ j;
                if (p > i) {
                    bool desc = (((base + i) & k) == 0);
                    ull A = sk[i], B = sk[p];
                    if ((A < B) == desc) { sk[i] = B; sk[p] = A; }
                }
            }
            __syncthreads();
        }
    for (int i = threadIdx.x; i < TILE; i += 1024) d_keys[base + i] = sk[i];
}

// all global steps (j >= 4096) of phase k, fused.
__global__ void __launch_bounds__(1024) kcol(int k) {
    __shared__ ull sk[4096];
    int lowbase = blockIdx.x * 128;
    for (int idx = threadIdx.x; idx < 4096; idx += 1024) {
        int m = idx >> 7, low = idx & 127;
        sk[idx] = d_keys[m * 4096 + lowbase + low];
    }
    __syncthreads();
    int kp = k >> 12;
    for (int jp = kp >> 1; jp >= 1; jp >>= 1) {
        for (int q = threadIdx.x; q < 2048; q += 1024) {
            int low = q & 127;
            int mg = q >> 7;
            int m = ((mg & ~(jp - 1)) << 1) | (mg & (jp - 1));
            int p = m | jp;
            bool desc = ((m & kp) == 0);
            ull A = sk[m * 128 + low], B = sk[p * 128 + low];
            if ((A < B) == desc) { sk[m * 128 + low] = B; sk[p * 128 + low] = A; }
        }
        __syncthreads();
    }
    for (int idx = threadIdx.x; idx < 4096; idx += 1024) {
        int m = idx >> 7, low = idx & 127;
        d_keys[m * 4096 + lowbase + low] = sk[idx];
    }
}

__global__ void __launch_bounds__(1024) ksort_merge(int k) {
    __shared__ ull sk[TILE];
    int base = blockIdx.x * TILE;
    for (int i = threadIdx.x; i < TILE; i += 1024) sk[i] = d_keys[base + i];
    __syncthreads();
    for (int j = TILE >> 1; j > 0; j >>= 1) {
        for (int i = threadIdx.x; i < TILE; i += 1024) {
            int p = i ^ j;
            if (p > i) {
                bool desc = (((base + i) & k) == 0);
                ull A = sk[i], B = sk[p];
                if ((A < B) == desc) { sk[i] = B; sk[p] = A; }
            }
        }
        __syncthreads();
    }
    for (int i = threadIdx.x; i < TILE; i += 1024) d_keys[base + i] = sk[i];
}

// top-K select: perm, inverse map, h2v[orig id] = tanh(s) * (h @ w2)
__global__ void kselect(const float* __restrict__ w2) {
    int r = (blockIdx.x * blockDim.x + threadIdx.x) >> 5;
    if (r >= KK) return;
    int lane = threadIdx.x & 31;
    ull key = d_keys[r];
    int idx = (int)(~(unsigned)(key & 0xFFFFFFFFull));
    if (lane == 0) { d_nidx[idx] = r; d_perm[r] = idx; }
    if (lane < NCLS) {
        float th = tanhf(d_s[idx]);
        float acc = 0.f;
#pragma unroll
        for (int j = 0; j < HID; j++)
            acc += d_h[idx * HID + j] * w2[j * NCLS + lane];
        ((float*)d_h2v)[idx * 12 + lane] = th * acc;
    }
}

// surviving-degree of kept nodes; pre-scale h2v rows by dinv2
__global__ void kdeg2() {
    int r = (blockIdx.x * blockDim.x + threadIdx.x) >> 5;
    if (r >= KK) return;
    int lane = threadIdx.x & 31;
    int i = d_perm[r];
    int st = d_rowptr[i], en = d_rowptr[i + 1];
    int cnt = 0;
    for (int e = st + lane; e < en; e += 32) cnt += (d_nidx[d_csr[e]] >= 0);
#pragma unroll
    for (int o = 16; o; o >>= 1) cnt += __shfl_xor_sync(0xFFFFFFFFu, cnt, o);
    float d2 = rsqrt_acc((float)(cnt + 1));
    if (lane == 0) d_dinv2[r] = d2;
    if (lane < 12) ((float*)d_h2v)[i * 12 + lane] *= d2;
}

// conv2: branch-free float4 gathers from dense h2v + relu + log_softmax
__global__ void kconv2(const float* __restrict__ b2, float* __restrict__ out) {
    __shared__ __align__(16) float red[8][12];
    int r = (blockIdx.x * blockDim.x + threadIdx.x) >> 5;
    if (r >= KK) return;
    int lane = threadIdx.x & 31, wip = (threadIdx.x >> 5) & 7;
    int i = d_perm[r];
    int st = d_rowptr[i], en = d_rowptr[i + 1];
    const float* h2vf = (const float*)d_h2v;
    float4 a0 = {0,0,0,0}, a1 = {0,0,0,0}, a2 = {0,0,0,0};
    for (int e = st + lane; e < en; e += 32) {
        int n = d_csr[e];
        const float4* row = (const float4*)(h2vf + n * 12);
        float4 v0 = row[0], v1 = row[1], v2 = row[2];
        a0.x += v0.x; a0.y += v0.y; a0.z += v0.z; a0.w += v0.w;
        a1.x += v1.x; a1.y += v1.y; a1.z += v1.z; a1.w += v1.w;
        a2.x += v2.x; a2.y += v2.y; a2.z += v2.z; a2.w += v2.w;
    }
#pragma unroll
    for (int o = 16; o; o >>= 1) {
        a0.x += __shfl_xor_sync(0xFFFFFFFFu, a0.x, o);
        a0.y += __shfl_xor_sync(0xFFFFFFFFu, a0.y, o);
        a0.z += __shfl_xor_sync(0xFFFFFFFFu, a0.z, o);
        a0.w += __shfl_xor_sync(0xFFFFFFFFu, a0.w, o);
        a1.x += __shfl_xor_sync(0xFFFFFFFFu, a1.x, o);
        a1.y += __shfl_xor_sync(0xFFFFFFFFu, a1.y, o);
        a1.z += __shfl_xor_sync(0xFFFFFFFFu, a1.z, o);
        a1.w += __shfl_xor_sync(0xFFFFFFFFu, a1.w, o);
        a2.x += __shfl_xor_sync(0xFFFFFFFFu, a2.x, o);
        a2.y += __shfl_xor_sync(0xFFFFFFFFu, a2.y, o);
    }
    if (lane == 0) {
        ((float4*)red[wip])[0] = a0;
        ((float4*)red[wip])[1] = a1;
        ((float4*)red[wip])[2] = a2;
    }
    __syncwarp();
    bool act = lane < NCLS;
    float own = act ? h2vf[i * 12 + lane] : 0.f;
    float v = act
        ? fmaxf(d_dinv2[r] * (red[wip][lane] + own) + b2[lane], 0.f)
        : -1e30f;
    float m = v;
#pragma unroll
    for (int o = 8; o; o >>= 1)
        m = fmaxf(m, __shfl_xor_sync(0xFFFFFFFFu, m, o, 16));
    float ex = act ? expf(v - m) : 0.f;
#pragma unroll
    for (int o = 8; o; o >>= 1)
        ex += __shfl_xor_sync(0xFFFFFFFFu, ex, o, 16);
    if (act) out[r * NCLS + lane] = v - m - logf(ex);
}

extern "C" void kernel_launch(void* const* d_in, const int* in_sizes, int n_in,
                              void* d_out, int out_size) {
    const float* x  = (const float*)d_in[0];
    const int*   ei = (const int*)d_in[1];
    const float* w1 = (const float*)d_in[2];
    const float* b1 = (const float*)d_in[3];
    const float* pw1 = (const float*)d_in[4];
    const float* pw2 = (const float*)d_in[5];
    const float* pb = (const float*)d_in[6];
    const float* w2 = (const float*)d_in[7];
    const float* b2 = (const float*)d_in[8];
    float* out = (float*)d_out;

    kcount<<<EE / 1024, 256>>>(ei);
    kscanA<<<NBLK, SBLK>>>();
    kscanC<<<NBLK, SBLK>>>();
    kgemm1<<<(NN + 255) / 256, 256>>>(x, w1);   // slot 4: gets profiled
    kscatter<<<EE / 1024, 256>>>(ei);
    kconv1<<<NN * 32 / 256, 256>>>(b1, pw1, pw2, pb);
    kpool<<<NN * 32 / 256, 256>>>();

    ksort_init<<<SSIZE / TILE, 1024>>>();
    for (int k = TILE * 2; k <= SSIZE; k <<= 1) {
        kcol<<<SSIZE / 4096, 1024>>>(k);
        ksort_merge<<<SSIZE / TILE, 1024>>>(k);
    }

    kselect<<<KK * 32 / 256, 256>>>(w2);
    kdeg2<<<KK * 32 / 256, 256>>>();
    kconv2<<<KK * 32 / 256, 256>>>(b2, out);
}

// round 16
// speedup vs baseline: 1.1213x; 1.0722x over previous
#include <cuda_runtime.h>
#include <math.h>

#define NN 100000
#define EE 3200000
#define HID 16
#define NCLS 10
#define KK 50000
#define SSIZE 131072
#define TILE2 2048
#define SBLK 1024
#define NBLK 98   // ceil(100000/1024)

typedef unsigned long long ull;

__device__ float  d_h0[NN * HID];
__device__ float  d_g0[NN * HID];     // dinv[n] * h0[n][ch]
__device__ float  d_h[NN * HID];
__device__ int    d_cnt[NN];          // zero at load; scanC re-zeroes each exec
__device__ int    d_rowptr[NN + 1];
__device__ float  d_dinv[NN];
__device__ int    d_csr[EE];
__device__ int    d_rank[EE];
__device__ float  d_spart[NN];
__device__ float  d_t2[NN];
__device__ float  d_s[NN];
__device__ ull    d_keys[SSIZE];      // zero at load; sort permutes zero tail in place
__device__ int    d_nidx[NN];
__device__ int    d_perm[KK];
__device__ float4 d_h2v[NN * 3];
__device__ float  d_dinv2[KK];
__device__ int    d_bsum[NBLK];

__device__ __forceinline__ void kadd(float& s, float& c, float v) {
    float y = v - c;
    float t = s + y;
    c = (t - s) - y;
    s = t;
}

__device__ __forceinline__ float rsqrt_acc(float x) {
    float r = rsqrtf(x);
    return r * (1.5f - 0.5f * x * r * r);
}

// h0 = x @ w1 (f32x2 packed FMA); epilogue writes g0 = dinv * h0
__global__ void __launch_bounds__(256) kgemm1(const float* __restrict__ x,
                                              const float* __restrict__ w1) {
    __shared__ __align__(16) float xsbuf[2 * (256 * 17) + 1];
    __shared__ __align__(16) float ws[2050];
    int t = threadIdx.x;
    for (int f = t; f < 2048; f += 256) {
        int kk = f >> 4;
        ws[f + ((kk >= 64) ? 2 : 0)] = w1[f];
    }
    const ull* wsu = (const ull*)ws;
    int base = blockIdx.x * 256;
    int p = t >> 1, h = t & 1;
    float* xs0 = xsbuf;
    float* xs1 = xsbuf + 256 * 17 + 1;
    ull a0[8], a1[8];
#pragma unroll
    for (int q8 = 0; q8 < 8; q8++) { a0[q8] = 0ull; a1[q8] = 0ull; }

    for (int it = 0; it < 4; it++) {
        __syncthreads();
#pragma unroll
        for (int half = 0; half < 2; half++) {
            int kq0 = (half * 4 + it) * 4;
            float* dst = half ? xs1 : xs0;
#pragma unroll
            for (int j = 0; j < 4; j++) {
                int idx = j * 256 + t;
                int row = idx >> 2, q = idx & 3;
                int rg = base + row; if (rg >= NN) rg = NN - 1;
                float4 v = ((const float4*)x)[rg * 32 + kq0 + q];
                float* xr = dst + row * 17 + q * 4;
                xr[0] = v.x; xr[1] = v.y; xr[2] = v.z; xr[3] = v.w;
            }
        }
        __syncthreads();
        const float* myxs = h ? xs1 : xs0;
        int prow = (p * 2) * 17;
#pragma unroll
        for (int k = 0; k < 16; k++) {
            float xv0 = myxs[prow + k];
            float xv1 = myxs[prow + 17 + k];
            ull xx0, xx1;
            asm("mov.b64 %0, {%1, %1};" : "=l"(xx0) : "r"(__float_as_uint(xv0)));
            asm("mov.b64 %0, {%1, %1};" : "=l"(xx1) : "r"(__float_as_uint(xv1)));
            int kk = (h * 4 + it) * 16 + k;
            int wb = kk * 8 + h;
#pragma unroll
            for (int q8 = 0; q8 < 8; q8++) {
                ull wv = wsu[wb + q8];
                asm("fma.rn.f32x2 %0, %1, %2, %0;" : "+l"(a0[q8]) : "l"(xx0), "l"(wv));
                asm("fma.rn.f32x2 %0, %1, %2, %0;" : "+l"(a1[q8]) : "l"(xx1), "l"(wv));
            }
        }
    }
#pragma unroll
    for (int q8 = 0; q8 < 8; q8++) {
        ull o0 = __shfl_xor_sync(0xFFFFFFFFu, a0[q8], 1);
        ull o1 = __shfl_xor_sync(0xFFFFFFFFu, a1[q8], 1);
        asm("add.rn.f32x2 %0, %0, %1;" : "+l"(a0[q8]) : "l"(o0));
        asm("add.rn.f32x2 %0, %0, %1;" : "+l"(a1[q8]) : "l"(o1));
    }
    if (h == 0) {
        int n0 = base + p * 2;
        if (n0 < NN) {
            ull dvp; unsigned dv = __float_as_uint(d_dinv[n0]);
            asm("mov.b64 %0, {%1, %1};" : "=l"(dvp) : "r"(dv));
            ull* o = (ull*)(d_h0 + (size_t)n0 * HID);
            ull* g = (ull*)(d_g0 + (size_t)n0 * HID);
#pragma unroll
            for (int q8 = 0; q8 < 8; q8++) {
                o[q8] = a0[q8];
                ull gv;
                asm("mul.rn.f32x2 %0, %1, %2;" : "=l"(gv) : "l"(a0[q8]), "l"(dvp));
                g[q8] = gv;
            }
        }
        if (n0 + 1 < NN) {
            ull dvp; unsigned dv = __float_as_uint(d_dinv[n0 + 1]);
            asm("mov.b64 %0, {%1, %1};" : "=l"(dvp) : "r"(dv));
            ull* o = (ull*)(d_h0 + (size_t)(n0 + 1) * HID);
            ull* g = (ull*)(d_g0 + (size_t)(n0 + 1) * HID);
#pragma unroll
            for (int q8 = 0; q8 < 8; q8++) {
                o[q8] = a1[q8];
                ull gv;
                asm("mul.rn.f32x2 %0, %1, %2;" : "=l"(gv) : "l"(a1[q8]), "l"(dvp));
                g[q8] = gv;
            }
        }
    }
}

// count in-degrees; record each edge's rank within its dst bucket
__global__ void kcount(const int* __restrict__ ei) {
    int e4 = blockIdx.x * blockDim.x + threadIdx.x;
    int4 d = ((const int4*)(ei + EE))[e4];
    int4 r;
    r.x = atomicAdd(&d_cnt[d.x], 1);
    r.y = atomicAdd(&d_cnt[d.y], 1);
    r.z = atomicAdd(&d_cnt[d.z], 1);
    r.w = atomicAdd(&d_cnt[d.w], 1);
    ((int4*)d_rank)[e4] = r;
}

__global__ void __launch_bounds__(SBLK) kscanA() {
    __shared__ int ws[32];
    int i = blockIdx.x * SBLK + threadIdx.x;
    int lane = threadIdx.x & 31, wd = threadIdx.x >> 5;
    int v = (i < NN) ? d_cnt[i] : 0;
    int s = v;
#pragma unroll
    for (int o = 16; o; o >>= 1) s += __shfl_xor_sync(0xFFFFFFFFu, s, o);
    if (lane == 0) ws[wd] = s;
    __syncthreads();
    if (wd == 0) {
        int s2 = ws[lane];
#pragma unroll
        for (int o = 16; o; o >>= 1) s2 += __shfl_xor_sync(0xFFFFFFFFu, s2, o);
        if (lane == 0) d_bsum[blockIdx.x] = s2;
    }
}

__global__ void __launch_bounds__(SBLK) kscanC() {
    __shared__ int ws[32];
    __shared__ int off_s;
    int bid = blockIdx.x;
    int t = threadIdx.x, lane = t & 31, wd = t >> 5;
    if (wd == 0) {
        int acc = 0;
        for (int b = lane; b < bid; b += 32) acc += d_bsum[b];
#pragma unroll
        for (int o = 16; o; o >>= 1) acc += __shfl_xor_sync(0xFFFFFFFFu, acc, o);
        if (lane == 0) {
            off_s = acc;
            if (bid == NBLK - 1) d_rowptr[NN] = acc + d_bsum[NBLK - 1];
        }
    }
    int i = bid * SBLK + t;
    int v = (i < NN) ? d_cnt[i] : 0;
    int xv = v;
#pragma unroll
    for (int o = 1; o < 32; o <<= 1) {
        int y = __shfl_up_sync(0xFFFFFFFFu, xv, o);
        if (lane >= o) xv += y;
    }
    if (lane == 31) ws[wd] = xv;
    __syncthreads();
    if (wd == 0) {
        int s2 = ws[lane];
#pragma unroll
        for (int o = 1; o < 32; o <<= 1) {
            int y = __shfl_up_sync(0xFFFFFFFFu, s2, o);
            if (lane >= o) s2 += y;
        }
        ws[lane] = s2;
    }
    __syncthreads();
    int excl = xv - v + (wd > 0 ? ws[wd - 1] : 0) + off_s;
    if (i < NN) {
        d_rowptr[i] = excl;
        d_dinv[i] = rsqrt_acc((float)(v + 1));
        d_nidx[i] = -1;
        d_cnt[i] = 0;
    }
}

// atomic-free scatter: position = rowptr[dst] + rank[edge]
__global__ void kscatter(const int* __restrict__ ei) {
    int e4 = blockIdx.x * blockDim.x + threadIdx.x;
    int4 s = ((const int4*)ei)[e4];
    int4 d = ((const int4*)(ei + EE))[e4];
    int4 r = ((const int4*)d_rank)[e4];
    d_csr[d_rowptr[d.x] + r.x] = s.x;
    d_csr[d_rowptr[d.y] + r.y] = s.y;
    d_csr[d_rowptr[d.z] + r.z] = s.z;
    d_csr[d_rowptr[d.w] + r.w] = s.w;
}

// conv1 (+relu): Kahan over precomputed g0 gathers; score linear terms fused
__global__ void kconv1(const float* __restrict__ b1, const float* __restrict__ pw1,
                       const float* __restrict__ pw2, const float* __restrict__ pb) {
    int gw = (blockIdx.x * blockDim.x + threadIdx.x) >> 5;
    if (gw >= NN) return;
    int lane = threadIdx.x & 31, half = lane >> 4, ch = lane & 15;
    int st = d_rowptr[gw], en = d_rowptr[gw + 1];
    float s0a = 0.f, c0a = 0.f, s1a = 0.f, c1a = 0.f;
    float s2a = 0.f, c2a = 0.f, s3a = 0.f, c3a = 0.f;
    int e = st + half;
    for (; e + 6 < en; e += 8) {
        int n0 = d_csr[e], n1 = d_csr[e + 2], n2 = d_csr[e + 4], n3 = d_csr[e + 6];
        kadd(s0a, c0a, d_g0[n0 * HID + ch]);
        kadd(s1a, c1a, d_g0[n1 * HID + ch]);
        kadd(s2a, c2a, d_g0[n2 * HID + ch]);
        kadd(s3a, c3a, d_g0[n3 * HID + ch]);
    }
    for (; e < en; e += 2) {
        int n0 = d_csr[e];
        kadd(s0a, c0a, d_g0[n0 * HID + ch]);
    }
    kadd(s0a, c0a, s1a); kadd(s0a, c0a, -c1a);
    kadd(s0a, c0a, s2a); kadd(s0a, c0a, -c2a);
    kadd(s0a, c0a, s3a); kadd(s0a, c0a, -c3a);
    float os = __shfl_xor_sync(0xFFFFFFFFu, s0a, 16);
    float oc = __shfl_xor_sync(0xFFFFFFFFu, c0a, 16);
    kadd(s0a, c0a, os); kadd(s0a, c0a, -oc);
    float a = s0a - c0a;
    float degf = (float)(en - st + 1);
    float hv = d_dinv[gw] * a + d_h0[gw * HID + ch] / degf + b1[ch];
    hv = fmaxf(hv, 0.f);
    if (half == 0) d_h[gw * HID + ch] = hv;
    float u1 = hv * pw1[ch];
    float u2 = hv * pw2[ch];
#pragma unroll
    for (int o = 8; o; o >>= 1) {
        u1 += __shfl_xor_sync(0xFFFFFFFFu, u1, o);
        u2 += __shfl_xor_sync(0xFFFFFFFFu, u2, o);
    }
    if (lane == 0) { d_spart[gw] = u1 + pb[0]; d_t2[gw] = u2; }
}

// score = spart + sum_{in-neighbors} t2 (Kahan); build sort key
__global__ void kpool() {
    int gw = (blockIdx.x * blockDim.x + threadIdx.x) >> 5;
    if (gw >= NN) return;
    int lane = threadIdx.x & 31;
    int st = d_rowptr[gw], en = d_rowptr[gw + 1];
    float sum = 0.f, comp = 0.f;
    for (int e = st + lane; e < en; e += 32) kadd(sum, comp, d_t2[d_csr[e]]);
#pragma unroll
    for (int o = 16; o; o >>= 1) {
        float os = __shfl_xor_sync(0xFFFFFFFFu, sum, o);
        float oc = __shfl_xor_sync(0xFFFFFFFFu, comp, o);
        kadd(sum, comp, os); kadd(sum, comp, -oc);
    }
    if (lane == 0) {
        float sv = d_spart[gw] + (sum - comp);
        d_s[gw] = sv;
        unsigned u = __float_as_uint(sv);
        u = (u & 0x80000000u) ? ~u : (u | 0x80000000u);
        d_keys[gw] = ((ull)u << 32) | (ull)(~(unsigned)gw);
    }
}

// bitonic sort, descending. TILE2=2048, 512 threads, 64 blocks (1 per SM):
// per-step smem traffic 32KB -> ~256cyc, half the 4096-tile cost.
__global__ void __launch_bounds__(512) ksort_init() {
    __shared__ ull sk[TILE2];
    int base = blockIdx.x * TILE2;
    for (int i = threadIdx.x; i < TILE2; i += 512) sk[i] = d_keys[base + i];
    __syncthreads();
    for (int k = 2; k <= TILE2; k <<= 1)
        for (int j = k >> 1; j > 0; j >>= 1) {
            for (int i = threadIdx.x; i < TILE2; i += 512) {
                int p = i ^ j;
                if (p > i) {
                    bool desc = (((base + i) & k) == 0);
                    ull A = sk[i], B = sk[p];
                    if ((A < B) == desc) { sk[i] = B; sk[p] = A; }
                }
            }
            __syncthreads();
        }
    for (int i = threadIdx.x; i < TILE2; i += 512) d_keys[base + i] = sk[i];
}

// all global steps (j >= 2048) of phase k, fused. Block owns strided set
// { m*2048 + lowbase + low : m in [0,64), low in [0,32) }.
__global__ void __launch_bounds__(512) kcol(int k) {
    __shared__ ull sk[2048];          // [m][low] : 64 x 32
    int lowbase = blockIdx.x * 32;
    for (int idx = threadIdx.x; idx < 2048; idx += 512) {
        int m = idx >> 5, low = idx & 31;
        sk[idx] = d_keys[m * 2048 + lowbase + low];
    }
    __syncthreads();
    int kp = k >> 11;                 // k in units of 2048
    for (int jp = kp >> 1; jp >= 1; jp >>= 1) {
        for (int q = threadIdx.x; q < 1024; q += 512) {
            int low = q & 31;
            int mg = q >> 5;          // 0..31
            int m = ((mg & ~(jp - 1)) << 1) | (mg & (jp - 1));
            int p = m | jp;
            bool desc = ((m & kp) == 0);
            ull A = sk[m * 32 + low], B = sk[p * 32 + low];
            if ((A < B) == desc) { sk[m * 32 + low] = B; sk[p * 32 + low] = A; }
        }
        __syncthreads();
    }
    for (int idx = threadIdx.x; idx < 2048; idx += 512) {
        int m = idx >> 5, low = idx & 31;
        d_keys[m * 2048 + lowbase + low] = sk[idx];
    }
}

__global__ void __launch_bounds__(512) ksort_merge(int k) {
    __shared__ ull sk[TILE2];
    int base = blockIdx.x * TILE2;
    for (int i = threadIdx.x; i < TILE2; i += 512) sk[i] = d_keys[base + i];
    __syncthreads();
    for (int j = TILE2 >> 1; j > 0; j >>= 1) {
        for (int i = threadIdx.x; i < TILE2; i += 512) {
            int p = i ^ j;
            if (p > i) {
                bool desc = (((base + i) & k) == 0);
                ull A = sk[i], B = sk[p];
                if ((A < B) == desc) { sk[i] = B; sk[p] = A; }
            }
        }
        __syncthreads();
    }
    for (int i = threadIdx.x; i < TILE2; i += 512) d_keys[base + i] = sk[i];
}

// top-K select: perm, inverse map, h2v[orig id] = tanh(s) * (h @ w2)
__global__ void kselect(const float* __restrict__ w2) {
    int r = (blockIdx.x * blockDim.x + threadIdx.x) >> 5;
    if (r >= KK) return;
    int lane = threadIdx.x & 31;
    ull key = d_keys[r];
    int idx = (int)(~(unsigned)(key & 0xFFFFFFFFull));
    if (lane == 0) { d_nidx[idx] = r; d_perm[r] = idx; }
    if (lane < NCLS) {
        float th = tanhf(d_s[idx]);
        float acc = 0.f;
#pragma unroll
        for (int j = 0; j < HID; j++)
            acc += d_h[idx * HID + j] * w2[j * NCLS + lane];
        ((float*)d_h2v)[idx * 12 + lane] = th * acc;
    }
}

// surviving-degree of kept nodes; pre-scale h2v rows by dinv2
__global__ void kdeg2() {
    int r = (blockIdx.x * blockDim.x + threadIdx.x) >> 5;
    if (r >= KK) return;
    int lane = threadIdx.x & 31;
    int i = d_perm[r];
    int st = d_rowptr[i], en = d_rowptr[i + 1];
    int cnt = 0;
    for (int e = st + lane; e < en; e += 32) cnt += (d_nidx[d_csr[e]] >= 0);
#pragma unroll
    for (int o = 16; o; o >>= 1) cnt += __shfl_xor_sync(0xFFFFFFFFu, cnt, o);
    float d2 = rsqrt_acc((float)(cnt + 1));
    if (lane == 0) d_dinv2[r] = d2;
    if (lane < 12) ((float*)d_h2v)[i * 12 + lane] *= d2;
}

// conv2: branch-free float4 gathers from dense h2v + relu + log_softmax
__global__ void kconv2(const float* __restrict__ b2, float* __restrict__ out) {
    __shared__ __align__(16) float red[8][12];
    int r = (blockIdx.x * blockDim.x + threadIdx.x) >> 5;
    if (r >= KK) return;
    int lane = threadIdx.x & 31, wip = (threadIdx.x >> 5) & 7;
    int i = d_perm[r];
    int st = d_rowptr[i], en = d_rowptr[i + 1];
    const float* h2vf = (const float*)d_h2v;
    float4 a0 = {0,0,0,0}, a1 = {0,0,0,0}, a2 = {0,0,0,0};
    for (int e = st + lane; e < en; e += 32) {
        int n = d_csr[e];
        const float4* row = (const float4*)(h2vf + n * 12);
        float4 v0 = row[0], v1 = row[1], v2 = row[2];
        a0.x += v0.x; a0.y += v0.y; a0.z += v0.z; a0.w += v0.w;
        a1.x += v1.x; a1.y += v1.y; a1.z += v1.z; a1.w += v1.w;
        a2.x += v2.x; a2.y += v2.y; a2.z += v2.z; a2.w += v2.w;
    }
#pragma unroll
    for (int o = 16; o; o >>= 1) {
        a0.x += __shfl_xor_sync(0xFFFFFFFFu, a0.x, o);
        a0.y += __shfl_xor_sync(0xFFFFFFFFu, a0.y, o);
        a0.z += __shfl_xor_sync(0xFFFFFFFFu, a0.z, o);
        a0.w += __shfl_xor_sync(0xFFFFFFFFu, a0.w, o);
        a1.x += __shfl_xor_sync(0xFFFFFFFFu, a1.x, o);
        a1.y += __shfl_xor_sync(0xFFFFFFFFu, a1.y, o);
        a1.z += __shfl_xor_sync(0xFFFFFFFFu, a1.z, o);
        a1.w += __shfl_xor_sync(0xFFFFFFFFu, a1.w, o);
        a2.x += __shfl_xor_sync(0xFFFFFFFFu, a2.x, o);
        a2.y += __shfl_xor_sync(0xFFFFFFFFu, a2.y, o);
    }
    if (lane == 0) {
        ((float4*)red[wip])[0] = a0;
        ((float4*)red[wip])[1] = a1;
        ((float4*)red[wip])[2] = a2;
    }
    __syncwarp();
    bool act = lane < NCLS;
    float own = act ? h2vf[i * 12 + lane] : 0.f;
    float v = act
        ? fmaxf(d_dinv2[r] * (red[wip][lane] + own) + b2[lane], 0.f)
        : -1e30f;
    float m = v;
#pragma unroll
    for (int o = 8; o; o >>= 1)
        m = fmaxf(m, __shfl_xor_sync(0xFFFFFFFFu, m, o, 16));
    float ex = act ? expf(v - m) : 0.f;
#pragma unroll
    for (int o = 8; o; o >>= 1)
        ex += __shfl_xor_sync(0xFFFFFFFFu, ex, o, 16);
    if (act) out[r * NCLS + lane] = v - m - logf(ex);
}

extern "C" void kernel_launch(void* const* d_in, const int* in_sizes, int n_in,
                              void* d_out, int out_size) {
    const float* x  = (const float*)d_in[0];
    const int*   ei = (const int*)d_in[1];
    const float* w1 = (const float*)d_in[2];
    const float* b1 = (const float*)d_in[3];
    const float* pw1 = (const float*)d_in[4];
    const float* pw2 = (const float*)d_in[5];
    const float* pb = (const float*)d_in[6];
    const float* w2 = (const float*)d_in[7];
    const float* b2 = (const float*)d_in[8];
    float* out = (float*)d_out;

    kcount<<<EE / 1024, 256>>>(ei);
    kscanA<<<NBLK, SBLK>>>();
    kscanC<<<NBLK, SBLK>>>();
    kgemm1<<<(NN + 255) / 256, 256>>>(x, w1);   // slot 4: gets profiled
    kscatter<<<EE / 1024, 256>>>(ei);
    kconv1<<<NN * 32 / 256, 256>>>(b1, pw1, pw2, pb);
    kpool<<<NN * 32 / 256, 256>>>();

    ksort_init<<<SSIZE / TILE2, 512>>>();
    for (int k = TILE2 * 2; k <= SSIZE; k <<= 1) {
        kcol<<<SSIZE / 2048, 512>>>(k);
        ksort_merge<<<SSIZE / TILE2, 512>>>(k);
    }

    kselect<<<KK * 32 / 256, 256>>>(w2);
    kdeg2<<<KK * 32 / 256, 256>>>();
    kconv2<<<KK * 32 / 256, 256>>>(b2, out);
}

// round 17
// speedup vs baseline: 1.2185x; 1.0867x over previous
#include <cuda_runtime.h>
#include <math.h>

#define NN 100000
#define EE 3200000
#define HID 16
#define NCLS 10
#define KK 50000
#define SSIZE 131072
#define TILE1 1024
#define SBLK 1024
#define NBLK 98   // ceil(100000/1024)

typedef unsigned long long ull;

__device__ float  d_h0[NN * HID];
__device__ float  d_g0[NN * HID];     // dinv[n] * h0[n][ch]
__device__ float  d_h[NN * HID];
__device__ int    d_cnt[NN];          // zero at load; scanC re-zeroes each exec
__device__ int    d_rowptr[NN + 1];
__device__ float  d_dinv[NN];
__device__ int    d_csr[EE];
__device__ int    d_rank[EE];
__device__ float  d_spart[NN];
__device__ float  d_t2[NN];
__device__ float  d_s[NN];
__device__ ull    d_keys[SSIZE];      // zero at load; sort permutes zero tail in place
__device__ int    d_nidx[NN];
__device__ int    d_perm[KK];
__device__ float4 d_h2v[NN * 3];
__device__ float  d_dinv2[KK];
__device__ int    d_bsum[NBLK];

__device__ __forceinline__ void kadd(float& s, float& c, float v) {
    float y = v - c;
    float t = s + y;
    c = (t - s) - y;
    s = t;
}

__device__ __forceinline__ float rsqrt_acc(float x) {
    float r = rsqrtf(x);
    return r * (1.5f - 0.5f * x * r * r);
}

// h0 = x @ w1 (f32x2 packed FMA); epilogue writes g0 = dinv * h0
__global__ void __launch_bounds__(256) kgemm1(const float* __restrict__ x,
                                              const float* __restrict__ w1) {
    __shared__ __align__(16) float xsbuf[2 * (256 * 17) + 1];
    __shared__ __align__(16) float ws[2050];
    int t = threadIdx.x;
    for (int f = t; f < 2048; f += 256) {
        int kk = f >> 4;
        ws[f + ((kk >= 64) ? 2 : 0)] = w1[f];
    }
    const ull* wsu = (const ull*)ws;
    int base = blockIdx.x * 256;
    int p = t >> 1, h = t & 1;
    float* xs0 = xsbuf;
    float* xs1 = xsbuf + 256 * 17 + 1;
    ull a0[8], a1[8];
#pragma unroll
    for (int q8 = 0; q8 < 8; q8++) { a0[q8] = 0ull; a1[q8] = 0ull; }

    for (int it = 0; it < 4; it++) {
        __syncthreads();
#pragma unroll
        for (int half = 0; half < 2; half++) {
            int kq0 = (half * 4 + it) * 4;
            float* dst = half ? xs1 : xs0;
#pragma unroll
            for (int j = 0; j < 4; j++) {
                int idx = j * 256 + t;
                int row = idx >> 2, q = idx & 3;
                int rg = base + row; if (rg >= NN) rg = NN - 1;
                float4 v = ((const float4*)x)[rg * 32 + kq0 + q];
                float* xr = dst + row * 17 + q * 4;
                xr[0] = v.x; xr[1] = v.y; xr[2] = v.z; xr[3] = v.w;
            }
        }
        __syncthreads();
        const float* myxs = h ? xs1 : xs0;
        int prow = (p * 2) * 17;
#pragma unroll
        for (int k = 0; k < 16; k++) {
            float xv0 = myxs[prow + k];
            float xv1 = myxs[prow + 17 + k];
            ull xx0, xx1;
            asm("mov.b64 %0, {%1, %1};" : "=l"(xx0) : "r"(__float_as_uint(xv0)));
            asm("mov.b64 %0, {%1, %1};" : "=l"(xx1) : "r"(__float_as_uint(xv1)));
            int kk = (h * 4 + it) * 16 + k;
            int wb = kk * 8 + h;
#pragma unroll
            for (int q8 = 0; q8 < 8; q8++) {
                ull wv = wsu[wb + q8];
                asm("fma.rn.f32x2 %0, %1, %2, %0;" : "+l"(a0[q8]) : "l"(xx0), "l"(wv));
                asm("fma.rn.f32x2 %0, %1, %2, %0;" : "+l"(a1[q8]) : "l"(xx1), "l"(wv));
            }
        }
    }
#pragma unroll
    for (int q8 = 0; q8 < 8; q8++) {
        ull o0 = __shfl_xor_sync(0xFFFFFFFFu, a0[q8], 1);
        ull o1 = __shfl_xor_sync(0xFFFFFFFFu, a1[q8], 1);
        asm("add.rn.f32x2 %0, %0, %1;" : "+l"(a0[q8]) : "l"(o0));
        asm("add.rn.f32x2 %0, %0, %1;" : "+l"(a1[q8]) : "l"(o1));
    }
    if (h == 0) {
        int n0 = base + p * 2;
        if (n0 < NN) {
            ull dvp; unsigned dv = __float_as_uint(d_dinv[n0]);
            asm("mov.b64 %0, {%1, %1};" : "=l"(dvp) : "r"(dv));
            ull* o = (ull*)(d_h0 + (size_t)n0 * HID);
            ull* g = (ull*)(d_g0 + (size_t)n0 * HID);
#pragma unroll
            for (int q8 = 0; q8 < 8; q8++) {
                o[q8] = a0[q8];
                ull gv;
                asm("mul.rn.f32x2 %0, %1, %2;" : "=l"(gv) : "l"(a0[q8]), "l"(dvp));
                g[q8] = gv;
            }
        }
        if (n0 + 1 < NN) {
            ull dvp; unsigned dv = __float_as_uint(d_dinv[n0 + 1]);
            asm("mov.b64 %0, {%1, %1};" : "=l"(dvp) : "r"(dv));
            ull* o = (ull*)(d_h0 + (size_t)(n0 + 1) * HID);
            ull* g = (ull*)(d_g0 + (size_t)(n0 + 1) * HID);
#pragma unroll
            for (int q8 = 0; q8 < 8; q8++) {
                o[q8] = a1[q8];
                ull gv;
                asm("mul.rn.f32x2 %0, %1, %2;" : "=l"(gv) : "l"(a1[q8]), "l"(dvp));
                g[q8] = gv;
            }
        }
    }
}

// count in-degrees; record each edge's rank within its dst bucket
__global__ void kcount(const int* __restrict__ ei) {
    int e4 = blockIdx.x * blockDim.x + threadIdx.x;
    int4 d = ((const int4*)(ei + EE))[e4];
    int4 r;
    r.x = atomicAdd(&d_cnt[d.x], 1);
    r.y = atomicAdd(&d_cnt[d.y], 1);
    r.z = atomicAdd(&d_cnt[d.z], 1);
    r.w = atomicAdd(&d_cnt[d.w], 1);
    ((int4*)d_rank)[e4] = r;
}

__global__ void __launch_bounds__(SBLK) kscanA() {
    __shared__ int ws[32];
    int i = blockIdx.x * SBLK + threadIdx.x;
    int lane = threadIdx.x & 31, wd = threadIdx.x >> 5;
    int v = (i < NN) ? d_cnt[i] : 0;
    int s = v;
#pragma unroll
    for (int o = 16; o; o >>= 1) s += __shfl_xor_sync(0xFFFFFFFFu, s, o);
    if (lane == 0) ws[wd] = s;
    __syncthreads();
    if (wd == 0) {
        int s2 = ws[lane];
#pragma unroll
        for (int o = 16; o; o >>= 1) s2 += __shfl_xor_sync(0xFFFFFFFFu, s2, o);
        if (lane == 0) d_bsum[blockIdx.x] = s2;
    }
}

__global__ void __launch_bounds__(SBLK) kscanC() {
    __shared__ int ws[32];
    __shared__ int off_s;
    int bid = blockIdx.x;
    int t = threadIdx.x, lane = t & 31, wd = t >> 5;
    if (wd == 0) {
        int acc = 0;
        for (int b = lane; b < bid; b += 32) acc += d_bsum[b];
#pragma unroll
        for (int o = 16; o; o >>= 1) acc += __shfl_xor_sync(0xFFFFFFFFu, acc, o);
        if (lane == 0) {
            off_s = acc;
            if (bid == NBLK - 1) d_rowptr[NN] = acc + d_bsum[NBLK - 1];
        }
    }
    int i = bid * SBLK + t;
    int v = (i < NN) ? d_cnt[i] : 0;
    int xv = v;
#pragma unroll
    for (int o = 1; o < 32; o <<= 1) {
        int y = __shfl_up_sync(0xFFFFFFFFu, xv, o);
        if (lane >= o) xv += y;
    }
    if (lane == 31) ws[wd] = xv;
    __syncthreads();
    if (wd == 0) {
        int s2 = ws[lane];
#pragma unroll
        for (int o = 1; o < 32; o <<= 1) {
            int y = __shfl_up_sync(0xFFFFFFFFu, s2, o);
            if (lane >= o) s2 += y;
        }
        ws[lane] = s2;
    }
    __syncthreads();
    int excl = xv - v + (wd > 0 ? ws[wd - 1] : 0) + off_s;
    if (i < NN) {
        d_rowptr[i] = excl;
        d_dinv[i] = rsqrt_acc((float)(v + 1));
        d_nidx[i] = -1;
        d_cnt[i] = 0;
    }
}

// atomic-free scatter: position = rowptr[dst] + rank[edge]
__global__ void kscatter(const int* __restrict__ ei) {
    int e4 = blockIdx.x * blockDim.x + threadIdx.x;
    int4 s = ((const int4*)ei)[e4];
    int4 d = ((const int4*)(ei + EE))[e4];
    int4 r = ((const int4*)d_rank)[e4];
    d_csr[d_rowptr[d.x] + r.x] = s.x;
    d_csr[d_rowptr[d.y] + r.y] = s.y;
    d_csr[d_rowptr[d.z] + r.z] = s.z;
    d_csr[d_rowptr[d.w] + r.w] = s.w;
}

// conv1 (+relu): Kahan over precomputed g0 gathers; score linear terms fused
__global__ void kconv1(const float* __restrict__ b1, const float* __restrict__ pw1,
                       const float* __restrict__ pw2, const float* __restrict__ pb) {
    int gw = (blockIdx.x * blockDim.x + threadIdx.x) >> 5;
    if (gw >= NN) return;
    int lane = threadIdx.x & 31, half = lane >> 4, ch = lane & 15;
    int st = d_rowptr[gw], en = d_rowptr[gw + 1];
    float s0a = 0.f, c0a = 0.f, s1a = 0.f, c1a = 0.f;
    float s2a = 0.f, c2a = 0.f, s3a = 0.f, c3a = 0.f;
    int e = st + half;
    for (; e + 6 < en; e += 8) {
        int n0 = d_csr[e], n1 = d_csr[e + 2], n2 = d_csr[e + 4], n3 = d_csr[e + 6];
        kadd(s0a, c0a, d_g0[n0 * HID + ch]);
        kadd(s1a, c1a, d_g0[n1 * HID + ch]);
        kadd(s2a, c2a, d_g0[n2 * HID + ch]);
        kadd(s3a, c3a, d_g0[n3 * HID + ch]);
    }
    for (; e < en; e += 2) {
        int n0 = d_csr[e];
        kadd(s0a, c0a, d_g0[n0 * HID + ch]);
    }
    kadd(s0a, c0a, s1a); kadd(s0a, c0a, -c1a);
    kadd(s0a, c0a, s2a); kadd(s0a, c0a, -c2a);
    kadd(s0a, c0a, s3a); kadd(s0a, c0a, -c3a);
    float os = __shfl_xor_sync(0xFFFFFFFFu, s0a, 16);
    float oc = __shfl_xor_sync(0xFFFFFFFFu, c0a, 16);
    kadd(s0a, c0a, os); kadd(s0a, c0a, -oc);
    float a = s0a - c0a;
    float degf = (float)(en - st + 1);
    float hv = d_dinv[gw] * a + d_h0[gw * HID + ch] / degf + b1[ch];
    hv = fmaxf(hv, 0.f);
    if (half == 0) d_h[gw * HID + ch] = hv;
    float u1 = hv * pw1[ch];
    float u2 = hv * pw2[ch];
#pragma unroll
    for (int o = 8; o; o >>= 1) {
        u1 += __shfl_xor_sync(0xFFFFFFFFu, u1, o);
        u2 += __shfl_xor_sync(0xFFFFFFFFu, u2, o);
    }
    if (lane == 0) { d_spart[gw] = u1 + pb[0]; d_t2[gw] = u2; }
}

// score = spart + sum_{in-neighbors} t2 (Kahan); build sort key
__global__ void kpool() {
    int gw = (blockIdx.x * blockDim.x + threadIdx.x) >> 5;
    if (gw >= NN) return;
    int lane = threadIdx.x & 31;
    int st = d_rowptr[gw], en = d_rowptr[gw + 1];
    float sum = 0.f, comp = 0.f;
    for (int e = st + lane; e < en; e += 32) kadd(sum, comp, d_t2[d_csr[e]]);
#pragma unroll
    for (int o = 16; o; o >>= 1) {
        float os = __shfl_xor_sync(0xFFFFFFFFu, sum, o);
        float oc = __shfl_xor_sync(0xFFFFFFFFu, comp, o);
        kadd(sum, comp, os); kadd(sum, comp, -oc);
    }
    if (lane == 0) {
        float sv = d_spart[gw] + (sum - comp);
        d_s[gw] = sv;
        unsigned u = __float_as_uint(sv);
        u = (u & 0x80000000u) ? ~u : (u | 0x80000000u);
        d_keys[gw] = ((ull)u << 32) | (ull)(~(unsigned)gw);
    }
}

// bitonic sort, descending. TILE1=1024, 512 threads, 128 blocks (~1/SM):
// per-step smem traffic 16KB -> ~128cyc.
__global__ void __launch_bounds__(512) ksort_init() {
    __shared__ ull sk[TILE1];
    int base = blockIdx.x * TILE1;
    for (int i = threadIdx.x; i < TILE1; i += 512) sk[i] = d_keys[base + i];
    __syncthreads();
    for (int k = 2; k <= TILE1; k <<= 1)
        for (int j = k >> 1; j > 0; j >>= 1) {
            for (int i = threadIdx.x; i < TILE1; i += 512) {
                int p = i ^ j;
                if (p > i) {
                    bool desc = (((base + i) & k) == 0);
                    ull A = sk[i], B = sk[p];
                    if ((A < B) == desc) { sk[i] = B; sk[p] = A; }
                }
            }
            __syncthreads();
        }
    for (int i = threadIdx.x; i < TILE1; i += 512) d_keys[base + i] = sk[i];
}

// all global steps (j >= 1024) of phase k, fused. Block owns strided set
// { m*1024 + lowbase + low : m in [0,128), low in [0,8) }.
__global__ void __launch_bounds__(512) kcol(int k) {
    __shared__ ull sk[1024];          // [m][low] : 128 x 8
    int lowbase = blockIdx.x * 8;
    for (int idx = threadIdx.x; idx < 1024; idx += 512) {
        int m = idx >> 3, low = idx & 7;
        sk[idx] = d_keys[m * 1024 + lowbase + low];
    }
    __syncthreads();
    int kp = k >> 10;                 // k in units of 1024
    for (int jp = kp >> 1; jp >= 1; jp >>= 1) {
        {
            int q = threadIdx.x;      // 512 pairs exactly
            int low = q & 7;
            int mg = q >> 3;          // 0..63
            int m = ((mg & ~(jp - 1)) << 1) | (mg & (jp - 1));
            int p = m | jp;
            bool desc = ((m & kp) == 0);
            ull A = sk[m * 8 + low], B = sk[p * 8 + low];
            if ((A < B) == desc) { sk[m * 8 + low] = B; sk[p * 8 + low] = A; }
        }
        __syncthreads();
    }
    for (int idx = threadIdx.x; idx < 1024; idx += 512) {
        int m = idx >> 3, low = idx & 7;
        d_keys[m * 1024 + lowbase + low] = sk[idx];
    }
}

__global__ void __launch_bounds__(512) ksort_merge(int k) {
    __shared__ ull sk[TILE1];
    int base = blockIdx.x * TILE1;
    for (int i = threadIdx.x; i < TILE1; i += 512) sk[i] = d_keys[base + i];
    __syncthreads();
    for (int j = TILE1 >> 1; j > 0; j >>= 1) {
        for (int i = threadIdx.x; i < TILE1; i += 512) {
            int p = i ^ j;
            if (p > i) {
                bool desc = (((base + i) & k) == 0);
                ull A = sk[i], B = sk[p];
                if ((A < B) == desc) { sk[i] = B; sk[p] = A; }
            }
        }
        __syncthreads();
    }
    for (int i = threadIdx.x; i < TILE1; i += 512) d_keys[base + i] = sk[i];
}

// top-K select: perm, inverse map, h2v[orig id] = tanh(s) * (h @ w2)
__global__ void kselect(const float* __restrict__ w2) {
    int r = (blockIdx.x * blockDim.x + threadIdx.x) >> 5;
    if (r >= KK) return;
    int lane = threadIdx.x & 31;
    ull key = d_keys[r];
    int idx = (int)(~(unsigned)(key & 0xFFFFFFFFull));
    if (lane == 0) { d_nidx[idx] = r; d_perm[r] = idx; }
    if (lane < NCLS) {
        float th = tanhf(d_s[idx]);
        float acc = 0.f;
#pragma unroll
        for (int j = 0; j < HID; j++)
            acc += d_h[idx * HID + j] * w2[j * NCLS + lane];
        ((float*)d_h2v)[idx * 12 + lane] = th * acc;
    }
}

// surviving-degree of kept nodes; pre-scale h2v rows by dinv2
__global__ void kdeg2() {
    int r = (blockIdx.x * blockDim.x + threadIdx.x) >> 5;
    if (r >= KK) return;
    int lane = threadIdx.x & 31;
    int i = d_perm[r];
    int st = d_rowptr[i], en = d_rowptr[i + 1];
    int cnt = 0;
    for (int e = st + lane; e < en; e += 32) cnt += (d_nidx[d_csr[e]] >= 0);
#pragma unroll
    for (int o = 16; o; o >>= 1) cnt += __shfl_xor_sync(0xFFFFFFFFu, cnt, o);
    float d2 = rsqrt_acc((float)(cnt + 1));
    if (lane == 0) d_dinv2[r] = d2;
    if (lane < 12) ((float*)d_h2v)[i * 12 + lane] *= d2;
}

// conv2: branch-free float4 gathers from dense h2v + relu + log_softmax
__global__ void kconv2(const float* __restrict__ b2, float* __restrict__ out) {
    __shared__ __align__(16) float red[8][12];
    int r = (blockIdx.x * blockDim.x + threadIdx.x) >> 5;
    if (r >= KK) return;
    int lane = threadIdx.x & 31, wip = (threadIdx.x >> 5) & 7;
    int i = d_perm[r];
    int st = d_rowptr[i], en = d_rowptr[i + 1];
    const float* h2vf = (const float*)d_h2v;
    float4 a0 = {0,0,0,0}, a1 = {0,0,0,0}, a2 = {0,0,0,0};
    for (int e = st + lane; e < en; e += 32) {
        int n = d_csr[e];
        const float4* row = (const float4*)(h2vf + n * 12);
        float4 v0 = row[0], v1 = row[1], v2 = row[2];
        a0.x += v0.x; a0.y += v0.y; a0.z += v0.z; a0.w += v0.w;
        a1.x += v1.x; a1.y += v1.y; a1.z += v1.z; a1.w += v1.w;
        a2.x += v2.x; a2.y += v2.y; a2.z += v2.z; a2.w += v2.w;
    }
#pragma unroll
    for (int o = 16; o; o >>= 1) {
        a0.x += __shfl_xor_sync(0xFFFFFFFFu, a0.x, o);
        a0.y += __shfl_xor_sync(0xFFFFFFFFu, a0.y, o);
        a0.z += __shfl_xor_sync(0xFFFFFFFFu, a0.z, o);
        a0.w += __shfl_xor_sync(0xFFFFFFFFu, a0.w, o);
        a1.x += __shfl_xor_sync(0xFFFFFFFFu, a1.x, o);
        a1.y += __shfl_xor_sync(0xFFFFFFFFu, a1.y, o);
        a1.z += __shfl_xor_sync(0xFFFFFFFFu, a1.z, o);
        a1.w += __shfl_xor_sync(0xFFFFFFFFu, a1.w, o);
        a2.x += __shfl_xor_sync(0xFFFFFFFFu, a2.x, o);
        a2.y += __shfl_xor_sync(0xFFFFFFFFu, a2.y, o);
    }
    if (lane == 0) {
        ((float4*)red[wip])[0] = a0;
        ((float4*)red[wip])[1] = a1;
        ((float4*)red[wip])[2] = a2;
    }
    __syncwarp();
    bool act = lane < NCLS;
    float own = act ? h2vf[i * 12 + lane] : 0.f;
    float v = act
        ? fmaxf(d_dinv2[r] * (red[wip][lane] + own) + b2[lane], 0.f)
        : -1e30f;
    float m = v;
#pragma unroll
    for (int o = 8; o; o >>= 1)
        m = fmaxf(m, __shfl_xor_sync(0xFFFFFFFFu, m, o, 16));
    float ex = act ? expf(v - m) : 0.f;
#pragma unroll
    for (int o = 8; o; o >>= 1)
        ex += __shfl_xor_sync(0xFFFFFFFFu, ex, o, 16);
    if (act) out[r * NCLS + lane] = v - m - logf(ex);
}

extern "C" void kernel_launch(void* const* d_in, const int* in_sizes, int n_in,
                              void* d_out, int out_size) {
    const float* x  = (const float*)d_in[0];
    const int*   ei = (const int*)d_in[1];
    const float* w1 = (const float*)d_in[2];
    const float* b1 = (const float*)d_in[3];
    const float* pw1 = (const float*)d_in[4];
    const float* pw2 = (const float*)d_in[5];
    const float* pb = (const float*)d_in[6];
    const float* w2 = (const float*)d_in[7];
    const float* b2 = (const float*)d_in[8];
    float* out = (float*)d_out;

    kcount<<<EE / 1024, 256>>>(ei);
    kscanA<<<NBLK, SBLK>>>();
    kscanC<<<NBLK, SBLK>>>();
    kgemm1<<<(NN + 255) / 256, 256>>>(x, w1);   // slot 4: gets profiled
    kscatter<<<EE / 1024, 256>>>(ei);
    kconv1<<<NN * 32 / 256, 256>>>(b1, pw1, pw2, pb);
    kpool<<<NN * 32 / 256, 256>>>();

    ksort_init<<<SSIZE / TILE1, 512>>>();
    for (int k = TILE1 * 2; k <= SSIZE; k <<= 1) {
        kcol<<<SSIZE / 1024, 512>>>(k);
        ksort_merge<<<SSIZE / TILE1, 512>>>(k);
    }

    kselect<<<KK * 32 / 256, 256>>>(w2);
    kdeg2<<<KK * 32 / 256, 256>>>();
    kconv2<<<KK * 32 / 256, 256>>>(b2, out);
}